// round 1
// baseline (speedup 1.0000x reference)
#include <cuda_runtime.h>
#include <math.h>
#include <stdint.h>

// Problem constants
#define B_  32
#define T_  512
#define C_  512
#define TD_ 256
#define G_  3
#define MROWS (B_ * C_)        // 16384 (== B_*T_ as well)
#define KF  (512 * 6)          // 3072 expanded-feature K for both KANs
#define NTOK 8388608           // B*T*C elements

// ----------------------------------------------------------------------------
// Scratch (device globals; no allocation at runtime)
// ----------------------------------------------------------------------------
__device__ float g_ln[NTOK];            // 32 MB  LN output (reused both stages)
__device__ float g_x1[NTOK];            // 32 MB  residual after token mixing
__device__ float g_F [(size_t)MROWS * KF];   // 192 MB feature matrix (reused)
__device__ float g_z [(size_t)MROWS * 1024]; // 64 MB  KAN output (reused)
__device__ float g_Bp[(size_t)1024 * KF];    // 12 MB  repacked coef (reused)

// ----------------------------------------------------------------------------
// LayerNorm: one block per row of C_=512, 256 threads (2 floats/thread)
// ----------------------------------------------------------------------------
__global__ void ln_kernel(const float* __restrict__ x,
                          const float* __restrict__ w,
                          const float* __restrict__ b,
                          float* __restrict__ out)
{
    int row = blockIdx.x;
    const float2* xr = (const float2*)(x + (size_t)row * C_);
    float2 v = xr[threadIdx.x];
    float s  = v.x + v.y;
    float sq = v.x * v.x + v.y * v.y;

    __shared__ float ss[8], sqq[8];
    __shared__ float s_mean, s_rstd;
    #pragma unroll
    for (int o = 16; o > 0; o >>= 1) {
        s  += __shfl_down_sync(0xffffffffu, s,  o);
        sq += __shfl_down_sync(0xffffffffu, sq, o);
    }
    int lane = threadIdx.x & 31, wid = threadIdx.x >> 5;
    if (lane == 0) { ss[wid] = s; sqq[wid] = sq; }
    __syncthreads();
    if (wid == 0) {
        float a = (lane < 8) ? ss[lane]  : 0.f;
        float q = (lane < 8) ? sqq[lane] : 0.f;
        #pragma unroll
        for (int o = 4; o > 0; o >>= 1) {
            a += __shfl_down_sync(0xffffffffu, a, o);
            q += __shfl_down_sync(0xffffffffu, q, o);
        }
        if (lane == 0) {
            float m = a * (1.0f / C_);
            float var = q * (1.0f / C_) - m * m;
            s_mean = m;
            s_rstd = rsqrtf(var + 1e-5f);
        }
    }
    __syncthreads();
    float m = s_mean, r = s_rstd;
    float2 wv = ((const float2*)w)[threadIdx.x];
    float2 bv = ((const float2*)b)[threadIdx.x];
    float2 ov;
    ov.x = (v.x - m) * r * wv.x + bv.x;
    ov.y = (v.y - m) * r * wv.y + bv.y;
    ((float2*)(out + (size_t)row * C_))[threadIdx.x] = ov;
}

// ----------------------------------------------------------------------------
// Repack coef (2, O, 512, 3) -> Bp (O x KF) row-major with k = i*6 + g*2 + trig
// ----------------------------------------------------------------------------
__global__ void pack_coef(const float* __restrict__ coef,
                          float* __restrict__ Bp, int O)
{
    int total = O * KF;
    int idx = blockIdx.x * blockDim.x + threadIdx.x;
    if (idx >= total) return;
    int o    = idx / KF;
    int r    = idx % KF;
    int i    = r / 6;
    int rr   = r % 6;
    int g    = rr >> 1;
    int trig = rr & 1;
    Bp[idx] = coef[(((size_t)trig * O + o) * 512 + i) * G_ + g];
}

// ----------------------------------------------------------------------------
// Feature expansion: per element v -> {cos kv, sin kv}_{k=1..3}
// TRANS=1: token stage, rows are (b,c), reads ln[b, i, c] (transposed)
// TRANS=0: channel stage, rows are (b,t), reads ln[m, c] directly
// ----------------------------------------------------------------------------
template<int TRANS>
__global__ void feat_kernel(const float* __restrict__ ln, float* __restrict__ F)
{
    int e = blockIdx.x * blockDim.x + threadIdx.x;     // 8,388,608 threads
    int i = e & 511;
    int n = e >> 9;
    float v;
    if (TRANS) {
        int b = n >> 9, c = n & 511;
        v = ln[((size_t)(b * T_ + i)) * C_ + c];
    } else {
        v = ln[e];
    }
    float s1, c1;
    sincosf(v, &s1, &c1);
    float c2 = 2.f * c1 * c1 - 1.f;
    float s2 = 2.f * s1 * c1;
    float c3 = 2.f * c1 * c2 - c1;
    float s3 = 2.f * c1 * s2 - s1;
    float2* p = (float2*)(F + (size_t)n * KF + i * 6);
    p[0] = make_float2(c1, s1);
    p[1] = make_float2(c2, s2);
    p[2] = make_float2(c3, s3);
}

// ----------------------------------------------------------------------------
// TN SGEMM: C[m,n] = sum_k A[m,k] * B[n,k] + bias[n]  (A: MxK, B: NxK row-major)
// 128x128 tile, BK=16, 256 threads, 8x8 per thread.
// MODE 0: Cout[m*N+n] = v
// MODE 1: token linear epilogue: m=(b,c), n=t ->
//         Cout[(b*T+t)*C+c] = res[(b*T+t)*C+c] + v
// MODE 2: channel linear epilogue: Cout[m*C+n] = res[m*C+n] + v
// ----------------------------------------------------------------------------
template<int MODE>
__global__ __launch_bounds__(256, 2)
void sgemm_tn(const float* __restrict__ A, const float* __restrict__ Bm,
              const float* __restrict__ bias, const float* __restrict__ res,
              float* __restrict__ Cout, int M, int N, int K)
{
    __shared__ float As[16][128];
    __shared__ float Bs[16][128];
    int m0  = blockIdx.y * 128;
    int n0  = blockIdx.x * 128;
    int tid = threadIdx.x;
    int tn  = (tid & 15) * 8;
    int tm  = (tid >> 4) * 8;
    float acc[8][8];
    #pragma unroll
    for (int x = 0; x < 8; x++)
        #pragma unroll
        for (int y = 0; y < 8; y++) acc[x][y] = 0.f;

    const float* Aptr = A  + (size_t)m0 * K;
    const float* Bptr = Bm + (size_t)n0 * K;

    for (int k0 = 0; k0 < K; k0 += 16) {
        #pragma unroll
        for (int l = 0; l < 2; l++) {
            int idx = tid + l * 256;
            int row = idx >> 2;
            int cv  = (idx & 3) * 4;
            float4 a = *(const float4*)(Aptr + (size_t)row * K + k0 + cv);
            As[cv + 0][row] = a.x; As[cv + 1][row] = a.y;
            As[cv + 2][row] = a.z; As[cv + 3][row] = a.w;
            float4 bq = *(const float4*)(Bptr + (size_t)row * K + k0 + cv);
            Bs[cv + 0][row] = bq.x; Bs[cv + 1][row] = bq.y;
            Bs[cv + 2][row] = bq.z; Bs[cv + 3][row] = bq.w;
        }
        __syncthreads();
        #pragma unroll
        for (int kk = 0; kk < 16; kk++) {
            float ra[8], rb[8];
            *(float4*)(ra)     = *(const float4*)&As[kk][tm];
            *(float4*)(ra + 4) = *(const float4*)&As[kk][tm + 4];
            *(float4*)(rb)     = *(const float4*)&Bs[kk][tn];
            *(float4*)(rb + 4) = *(const float4*)&Bs[kk][tn + 4];
            #pragma unroll
            for (int x = 0; x < 8; x++)
                #pragma unroll
                for (int y = 0; y < 8; y++)
                    acc[x][y] += ra[x] * rb[y];
        }
        __syncthreads();
    }

    #pragma unroll
    for (int x = 0; x < 8; x++) {
        int m = m0 + tm + x;
        #pragma unroll
        for (int y = 0; y < 8; y++) {
            int n = n0 + tn + y;
            float v = acc[x][y] + bias[n];
            if (MODE == 0) {
                Cout[(size_t)m * N + n] = v;
            } else if (MODE == 1) {
                int b = m >> 9, c = m & 511;
                size_t oi = ((size_t)(b * T_ + n)) * C_ + c;
                Cout[oi] = res[oi] + v;
            } else {
                size_t oi = (size_t)m * C_ + n;
                Cout[oi] = res[oi] + v;
            }
        }
    }
}

// ----------------------------------------------------------------------------
// Launch
// ----------------------------------------------------------------------------
extern "C" void kernel_launch(void* const* d_in, const int* in_sizes, int n_in,
                              void* d_out, int out_size)
{
    const float* x        = (const float*)d_in[0];
    const float* ln1_w    = (const float*)d_in[1];
    const float* ln1_b    = (const float*)d_in[2];
    const float* tok_coef = (const float*)d_in[3];
    const float* tok_kb   = (const float*)d_in[4];
    const float* tok_lw   = (const float*)d_in[5];
    const float* tok_lb   = (const float*)d_in[6];
    const float* ln2_w    = (const float*)d_in[7];
    const float* ln2_b    = (const float*)d_in[8];
    const float* ch_coef  = (const float*)d_in[9];
    const float* ch_kb    = (const float*)d_in[10];
    const float* ch_lw    = (const float*)d_in[11];
    const float* ch_lb    = (const float*)d_in[12];
    float* out = (float*)d_out;

    float *pLn, *pX1, *pF, *pZ, *pBp;
    cudaGetSymbolAddress((void**)&pLn, g_ln);
    cudaGetSymbolAddress((void**)&pX1, g_x1);
    cudaGetSymbolAddress((void**)&pF,  g_F);
    cudaGetSymbolAddress((void**)&pZ,  g_z);
    cudaGetSymbolAddress((void**)&pBp, g_Bp);

    const int M = MROWS;

    // ---- token mixing ----
    ln_kernel<<<B_ * T_, 256>>>(x, ln1_w, ln1_b, pLn);
    pack_coef<<<(TD_ * KF + 255) / 256, 256>>>(tok_coef, pBp, TD_);
    feat_kernel<1><<<NTOK / 256, 256>>>(pLn, pF);
    // z = F * coef^T + kbias  (M x 256)
    sgemm_tn<0><<<dim3(TD_ / 128, M / 128), 256>>>(pF, pBp, tok_kb, nullptr, pZ,
                                                   M, TD_, KF);
    // x1 = x + (z * lw^T + lb) transposed back to (B,T,C)
    sgemm_tn<1><<<dim3(T_ / 128, M / 128), 256>>>(pZ, tok_lw, tok_lb, x, pX1,
                                                  M, T_, TD_);

    // ---- channel mixing ----
    ln_kernel<<<B_ * T_, 256>>>(pX1, ln2_w, ln2_b, pLn);
    pack_coef<<<(1024 * KF + 255) / 256, 256>>>(ch_coef, pBp, 1024);
    feat_kernel<0><<<NTOK / 256, 256>>>(pLn, pF);
    // z2 = F * coef^T + kbias  (M x 1024)
    sgemm_tn<0><<<dim3(1024 / 128, M / 128), 256>>>(pF, pBp, ch_kb, nullptr, pZ,
                                                    M, 1024, KF);
    // out = x1 + (z2 * lw^T + lb)
    sgemm_tn<2><<<dim3(C_ / 128, M / 128), 256>>>(pZ, ch_lw, ch_lb, pX1, out,
                                                  M, C_, 1024);
}

// round 3
// speedup vs baseline: 2.8861x; 2.8861x over previous
#include <cuda_runtime.h>
#include <cuda_bf16.h>
#include <math.h>
#include <stdint.h>

// Problem constants
#define B_  32
#define T_  512
#define C_  512
#define TD_ 256
#define G_  3
#define MROWS (B_ * C_)        // 16384 (== B_*T_)
#define KF  (512 * 6)          // 3072 expanded-feature K
#define NTOK 8388608           // B*T*C

// GEMM tiling
#define MT 128
#define NT 256
#define BK 64                    // bf16 elems per chunk (128 bytes/row)
// smem per buffer: Ah 16K | Al 16K | Bh 32K | Bl 32K = 96K
#define OFF_AL 16384u
#define OFF_BH 32768u
#define OFF_BL 65536u
#define BUF_STRIDE 98304u
#define SMEM_SZ (2 * 98304)
#define STG_S 261               // stage row stride (floats), odd -> conflict-free cols

// ----------------------------------------------------------------------------
// PTX helpers (sm_100 base target: cp.async + ldmatrix + mma.sync only)
// ----------------------------------------------------------------------------
__device__ __forceinline__ uint32_t smem_u32(const void* p) {
    uint32_t a;
    asm("{ .reg .u64 t; cvta.to.shared.u64 t, %1; cvt.u32.u64 %0, t; }" : "=r"(a) : "l"(p));
    return a;
}
__device__ __forceinline__ void cpasync16(uint32_t dst, const void* src) {
    asm volatile("cp.async.cg.shared.global [%0], [%1], 16;" :: "r"(dst), "l"(src));
}
__device__ __forceinline__ void cp_commit() {
    asm volatile("cp.async.commit_group;" ::: "memory");
}
__device__ __forceinline__ void cp_wait1() {
    asm volatile("cp.async.wait_group 1;" ::: "memory");
}
__device__ __forceinline__ void cp_wait0() {
    asm volatile("cp.async.wait_group 0;" ::: "memory");
}
__device__ __forceinline__ void ldsm4(uint32_t addr, uint32_t r[4]) {
    asm volatile("ldmatrix.sync.aligned.m8n8.x4.shared.b16 {%0,%1,%2,%3}, [%4];"
                 : "=r"(r[0]), "=r"(r[1]), "=r"(r[2]), "=r"(r[3]) : "r"(addr));
}
__device__ __forceinline__ void mma16816(float d[4], const uint32_t a[4], const uint32_t b[2]) {
    asm volatile(
        "mma.sync.aligned.m16n8k16.row.col.f32.bf16.bf16.f32 "
        "{%0,%1,%2,%3}, {%4,%5,%6,%7}, {%8,%9}, {%0,%1,%2,%3};"
        : "+f"(d[0]), "+f"(d[1]), "+f"(d[2]), "+f"(d[3])
        : "r"(a[0]), "r"(a[1]), "r"(a[2]), "r"(a[3]), "r"(b[0]), "r"(b[1]));
}
__device__ __forceinline__ void split_bf(float v, __nv_bfloat16& h, __nv_bfloat16& l) {
    h = __float2bfloat16(v);
    l = __float2bfloat16(v - __bfloat162float(h));
}

// ----------------------------------------------------------------------------
// Scratch (device globals)
// ----------------------------------------------------------------------------
__device__ __nv_bfloat16 g_Fh[(size_t)MROWS * KF];   // 96 MB
__device__ __nv_bfloat16 g_Fl[(size_t)MROWS * KF];   // 96 MB
__device__ __nv_bfloat16 g_Zh[(size_t)MROWS * 1024]; // 32 MB
__device__ __nv_bfloat16 g_Zl[(size_t)MROWS * 1024]; // 32 MB
__device__ __nv_bfloat16 g_Bh[(size_t)1024 * KF];    // 6 MB
__device__ __nv_bfloat16 g_Bl[(size_t)1024 * KF];    // 6 MB
__device__ __nv_bfloat16 g_Wh[(size_t)512 * 1024];   // 1 MB
__device__ __nv_bfloat16 g_Wl[(size_t)512 * 1024];   // 1 MB
__device__ float g_ln[NTOK];                         // 32 MB
__device__ float g_x1[NTOK];                         // 32 MB

// ----------------------------------------------------------------------------
// LayerNorm: one block per row of C_=512, 256 threads
// ----------------------------------------------------------------------------
__global__ void ln_kernel(const float* __restrict__ x,
                          const float* __restrict__ w,
                          const float* __restrict__ b,
                          float* __restrict__ out)
{
    int row = blockIdx.x;
    const float2* xr = (const float2*)(x + (size_t)row * C_);
    float2 v = xr[threadIdx.x];
    float s  = v.x + v.y;
    float sq = v.x * v.x + v.y * v.y;

    __shared__ float ss[8], sqq[8];
    __shared__ float s_mean, s_rstd;
    #pragma unroll
    for (int o = 16; o > 0; o >>= 1) {
        s  += __shfl_down_sync(0xffffffffu, s,  o);
        sq += __shfl_down_sync(0xffffffffu, sq, o);
    }
    int lane = threadIdx.x & 31, wid = threadIdx.x >> 5;
    if (lane == 0) { ss[wid] = s; sqq[wid] = sq; }
    __syncthreads();
    if (wid == 0) {
        float a = (lane < 8) ? ss[lane]  : 0.f;
        float q = (lane < 8) ? sqq[lane] : 0.f;
        #pragma unroll
        for (int o = 4; o > 0; o >>= 1) {
            a += __shfl_down_sync(0xffffffffu, a, o);
            q += __shfl_down_sync(0xffffffffu, q, o);
        }
        if (lane == 0) {
            float m = a * (1.0f / C_);
            float var = q * (1.0f / C_) - m * m;
            s_mean = m;
            s_rstd = rsqrtf(var + 1e-5f);
        }
    }
    __syncthreads();
    float m = s_mean, r = s_rstd;
    float2 wv = ((const float2*)w)[threadIdx.x];
    float2 bv = ((const float2*)b)[threadIdx.x];
    float2 ov;
    ov.x = (v.x - m) * r * wv.x + bv.x;
    ov.y = (v.y - m) * r * wv.y + bv.y;
    ((float2*)(out + (size_t)row * C_))[threadIdx.x] = ov;
}

// ----------------------------------------------------------------------------
// Repack coef (2, O, 512, 3) -> hi/lo bf16 (O x KF), k = i*6 + g*2 + trig
// ----------------------------------------------------------------------------
__global__ void pack_coef(const float* __restrict__ coef,
                          __nv_bfloat16* __restrict__ Bh,
                          __nv_bfloat16* __restrict__ Bl, int O)
{
    int total = O * KF;
    int idx = blockIdx.x * blockDim.x + threadIdx.x;
    if (idx >= total) return;
    int o    = idx / KF;
    int r    = idx % KF;
    int i    = r / 6;
    int rr   = r % 6;
    int g    = rr >> 1;
    int trig = rr & 1;
    float v = coef[(((size_t)trig * O + o) * 512 + i) * G_ + g];
    split_bf(v, Bh[idx], Bl[idx]);
}

// fp32 -> bf16 hi/lo split (linear weights)
__global__ void pack_w(const float* __restrict__ w,
                       __nv_bfloat16* __restrict__ Wh,
                       __nv_bfloat16* __restrict__ Wl, int total)
{
    int idx = blockIdx.x * blockDim.x + threadIdx.x;
    if (idx >= total) return;
    split_bf(w[idx], Wh[idx], Wl[idx]);
}

// ----------------------------------------------------------------------------
// Feature expansion -> bf16 hi/lo. TRANS=1: rows (b,c) read ln transposed.
// ----------------------------------------------------------------------------
template<int TRANS>
__global__ void feat_kernel(const float* __restrict__ ln,
                            __nv_bfloat16* __restrict__ Fh,
                            __nv_bfloat16* __restrict__ Fl)
{
    int e = blockIdx.x * blockDim.x + threadIdx.x;
    int i = e & 511;
    int n = e >> 9;
    float v;
    if (TRANS) {
        int b = n >> 9, c = n & 511;
        v = ln[((size_t)(b * T_ + i)) * C_ + c];
    } else {
        v = ln[e];
    }
    float s1, c1;
    sincosf(v, &s1, &c1);
    float c2 = 2.f * c1 * c1 - 1.f;
    float s2 = 2.f * s1 * c1;
    float c3 = 2.f * c1 * c2 - c1;
    float s3 = 2.f * c1 * s2 - s1;
    float vals[6] = {c1, s1, c2, s2, c3, s3};
    __nv_bfloat162 hv[3], lv[3];
    #pragma unroll
    for (int q = 0; q < 3; q++) {
        __nv_bfloat16 h0, l0, h1, l1;
        split_bf(vals[2*q],   h0, l0);
        split_bf(vals[2*q+1], h1, l1);
        hv[q] = __nv_bfloat162(h0, h1);
        lv[q] = __nv_bfloat162(l0, l1);
    }
    size_t base = (size_t)n * KF + i * 6;
    __nv_bfloat162* ph = (__nv_bfloat162*)(Fh + base);
    __nv_bfloat162* pl = (__nv_bfloat162*)(Fl + base);
    ph[0] = hv[0]; ph[1] = hv[1]; ph[2] = hv[2];
    pl[0] = lv[0]; pl[1] = lv[1]; pl[2] = lv[2];
}

// ----------------------------------------------------------------------------
// bf16x3-split TN GEMM via mma.sync: D[m,n] = sum_k A[m,k]*B[n,k] + bias[n]
//   D = Ah*Bh + Ah*Bl + Al*Bh   (fp32 accum)
// CTA tile 128x256, BK=64, 8 warps (64x64 each), cp.async double buffer.
// MODE 0: write bf16 hi/lo split of D to outH/outL (row stride Ntot)
// MODE 1: token linear: m=(b,c), n=t; outF[(b*T+n)*C+c] = res[..] + D
// MODE 2: outF[m*C+n0+n] = res[..] + D
// ----------------------------------------------------------------------------
template<int MODE>
__global__ __launch_bounds__(256, 1)
void kan_gemm(const __nv_bfloat16* __restrict__ Ah, const __nv_bfloat16* __restrict__ Al,
              const __nv_bfloat16* __restrict__ Bh, const __nv_bfloat16* __restrict__ Bl,
              const float* __restrict__ bias, const float* __restrict__ res,
              float* __restrict__ outF,
              __nv_bfloat16* __restrict__ outH, __nv_bfloat16* __restrict__ outL,
              int K, int Ntot)
{
    extern __shared__ char smem[];
    const uint32_t sbase = smem_u32(smem);
    const int tid  = threadIdx.x;
    const int wid  = tid >> 5;
    const int lane = tid & 31;
    const int m0 = blockIdx.y * MT;
    const int n0 = blockIdx.x * NT;
    const int wm = wid >> 2;           // 0..1, 64 m-rows each
    const int wn = wid & 3;            // 0..3, 64 n-cols each

    float acc[4][8][4];
    #pragma unroll
    for (int i = 0; i < 4; i++)
        #pragma unroll
        for (int j = 0; j < 8; j++)
            #pragma unroll
            for (int q = 0; q < 4; q++) acc[i][j][q] = 0.f;

    const int NC = K >> 6;

    // ---- async chunk loader: global row-major -> 128B-row swizzled smem
    auto load_chunk = [&](int kc, int buf) {
        const uint32_t sb = sbase + (uint32_t)buf * BUF_STRIDE;
        const size_t kcol = (size_t)kc * BK;
        #pragma unroll
        for (int it = 0; it < 4; it++) {
            int u = tid + it * 256;
            int r = u >> 3, cch = u & 7;
            uint32_t off = r * 128 + ((cch ^ (r & 7)) << 4);
            const char* pa = (const char*)(Ah + (size_t)(m0 + r) * K + kcol) + cch * 16;
            cpasync16(sb + off, pa);
            const char* pl = (const char*)(Al + (size_t)(m0 + r) * K + kcol) + cch * 16;
            cpasync16(sb + OFF_AL + off, pl);
        }
        #pragma unroll
        for (int it = 0; it < 8; it++) {
            int u = tid + it * 256;
            int r = u >> 3, cch = u & 7;
            uint32_t off = r * 128 + ((cch ^ (r & 7)) << 4);
            const char* ph = (const char*)(Bh + (size_t)(n0 + r) * K + kcol) + cch * 16;
            cpasync16(sb + OFF_BH + off, ph);
            const char* plo = (const char*)(Bl + (size_t)(n0 + r) * K + kcol) + cch * 16;
            cpasync16(sb + OFF_BL + off, plo);
        }
        cp_commit();
    };

    load_chunk(0, 0);

    const int lr = lane & 7;
    const int lq = lane >> 3;          // 0..3 (ldmatrix matrix id)

    for (int kc = 0; kc < NC; kc++) {
        if (kc + 1 < NC) { load_chunk(kc + 1, (kc + 1) & 1); cp_wait1(); }
        else             { cp_wait0(); }
        __syncthreads();

        const uint32_t sb = sbase + (uint32_t)(kc & 1) * BUF_STRIDE;
        #pragma unroll
        for (int k16 = 0; k16 < 4; k16++) {
            uint32_t ah[4][4], al[4][4], bh[8][2], bl[8][2];
            // A fragments: q0/q1 -> rows +0/+8 chunk+0 ; q2/q3 -> rows +0/+8 chunk+1
            #pragma unroll
            for (int i = 0; i < 4; i++) {
                int row = wm * 64 + i * 16 + lr + (lq & 1) * 8;
                int ch  = (k16 * 2 + (lq >> 1)) ^ (row & 7);
                uint32_t ad = row * 128 + (ch << 4);
                ldsm4(sb + ad, ah[i]);
                ldsm4(sb + OFF_AL + ad, al[i]);
            }
            // B fragments: q0/q1 -> rows+0 chunk +0/+1 ; q2/q3 -> rows+8 chunk +0/+1
            #pragma unroll
            for (int jp = 0; jp < 4; jp++) {
                int row = wn * 64 + jp * 16 + lr + (lq >> 1) * 8;
                int ch  = (k16 * 2 + (lq & 1)) ^ (row & 7);
                uint32_t ad = row * 128 + (ch << 4);
                uint32_t t4[4];
                ldsm4(sb + OFF_BH + ad, t4);
                bh[2*jp][0] = t4[0]; bh[2*jp][1] = t4[1];
                bh[2*jp+1][0] = t4[2]; bh[2*jp+1][1] = t4[3];
                ldsm4(sb + OFF_BL + ad, t4);
                bl[2*jp][0] = t4[0]; bl[2*jp][1] = t4[1];
                bl[2*jp+1][0] = t4[2]; bl[2*jp+1][1] = t4[3];
            }
            #pragma unroll
            for (int i = 0; i < 4; i++)
                #pragma unroll
                for (int j = 0; j < 8; j++)
                    mma16816(acc[i][j], ah[i], bh[j]);
            #pragma unroll
            for (int i = 0; i < 4; i++)
                #pragma unroll
                for (int j = 0; j < 8; j++)
                    mma16816(acc[i][j], ah[i], bl[j]);
            #pragma unroll
            for (int i = 0; i < 4; i++)
                #pragma unroll
                for (int j = 0; j < 8; j++)
                    mma16816(acc[i][j], al[i], bh[j]);
        }
        __syncthreads();
    }

    // ---- stage accumulators to smem (reuse GEMM buffers)
    float* stage = (float*)smem;
    {
        const int g = lane >> 2, t2 = (lane & 3) * 2;
        #pragma unroll
        for (int i = 0; i < 4; i++) {
            int row = wm * 64 + i * 16 + g;
            #pragma unroll
            for (int j = 0; j < 8; j++) {
                int col = wn * 64 + j * 8 + t2;
                stage[row * STG_S + col]           = acc[i][j][0];
                stage[row * STG_S + col + 1]       = acc[i][j][1];
                stage[(row + 8) * STG_S + col]     = acc[i][j][2];
                stage[(row + 8) * STG_S + col + 1] = acc[i][j][3];
            }
        }
    }
    __syncthreads();

    if (MODE == 0) {
        // split-bf16 output, row stride Ntot
        for (int u = tid; u < 128 * (NT / 2); u += 256) {
            int r = u >> 7;                 // NT/2 == 128
            int c = (u & 127) * 2;
            float v0 = stage[r * STG_S + c]     + bias[n0 + c];
            float v1 = stage[r * STG_S + c + 1] + bias[n0 + c + 1];
            __nv_bfloat16 h0, l0, h1, l1;
            split_bf(v0, h0, l0);
            split_bf(v1, h1, l1);
            size_t o = ((size_t)(m0 + r) * Ntot + n0 + c) >> 1;
            ((__nv_bfloat162*)outH)[o] = __nv_bfloat162(h0, h1);
            ((__nv_bfloat162*)outL)[o] = __nv_bfloat162(l0, l1);
        }
    } else if (MODE == 2) {
        for (int u = tid; u < 128 * (NT / 4); u += 256) {
            int r = u >> 6;                 // NT/4 == 64
            int c = (u & 63) * 4;
            size_t base = (size_t)(m0 + r) * C_ + n0 + c;
            float4 rv = *(const float4*)(res + base);
            float4 ov;
            ov.x = rv.x + stage[r * STG_S + c]     + bias[n0 + c];
            ov.y = rv.y + stage[r * STG_S + c + 1] + bias[n0 + c + 1];
            ov.z = rv.z + stage[r * STG_S + c + 2] + bias[n0 + c + 2];
            ov.w = rv.w + stage[r * STG_S + c + 3] + bias[n0 + c + 3];
            *(float4*)(outF + base) = ov;
        }
    } else {
        // MODE 1: m=(b,c) rows, n=t cols; scatter transposed with residual
        const int b  = m0 >> 9;
        const int c0 = m0 & 511;
        for (int nl = wid; nl < NT; nl += 8) {
            int n = n0 + nl;
            float bn = bias[n];
            size_t obase = ((size_t)(b * T_ + n)) * C_ + c0;
            #pragma unroll
            for (int cc = 0; cc < 4; cc++) {
                int c = lane + cc * 32;
                float v = stage[c * STG_S + nl] + bn;
                outF[obase + c] = res[obase + c] + v;
            }
        }
    }
}

// ----------------------------------------------------------------------------
// Launch
// ----------------------------------------------------------------------------
extern "C" void kernel_launch(void* const* d_in, const int* in_sizes, int n_in,
                              void* d_out, int out_size)
{
    const float* x        = (const float*)d_in[0];
    const float* ln1_w    = (const float*)d_in[1];
    const float* ln1_b    = (const float*)d_in[2];
    const float* tok_coef = (const float*)d_in[3];
    const float* tok_kb   = (const float*)d_in[4];
    const float* tok_lw   = (const float*)d_in[5];
    const float* tok_lb   = (const float*)d_in[6];
    const float* ln2_w    = (const float*)d_in[7];
    const float* ln2_b    = (const float*)d_in[8];
    const float* ch_coef  = (const float*)d_in[9];
    const float* ch_kb    = (const float*)d_in[10];
    const float* ch_lw    = (const float*)d_in[11];
    const float* ch_lb    = (const float*)d_in[12];
    float* out = (float*)d_out;

    __nv_bfloat16 *pFh, *pFl, *pZh, *pZl, *pBh, *pBl, *pWh, *pWl;
    float *pLn, *pX1;
    cudaGetSymbolAddress((void**)&pFh, g_Fh);
    cudaGetSymbolAddress((void**)&pFl, g_Fl);
    cudaGetSymbolAddress((void**)&pZh, g_Zh);
    cudaGetSymbolAddress((void**)&pZl, g_Zl);
    cudaGetSymbolAddress((void**)&pBh, g_Bh);
    cudaGetSymbolAddress((void**)&pBl, g_Bl);
    cudaGetSymbolAddress((void**)&pWh, g_Wh);
    cudaGetSymbolAddress((void**)&pWl, g_Wl);
    cudaGetSymbolAddress((void**)&pLn, g_ln);
    cudaGetSymbolAddress((void**)&pX1, g_x1);

    cudaFuncSetAttribute(kan_gemm<0>, cudaFuncAttributeMaxDynamicSharedMemorySize, SMEM_SZ);
    cudaFuncSetAttribute(kan_gemm<1>, cudaFuncAttributeMaxDynamicSharedMemorySize, SMEM_SZ);
    cudaFuncSetAttribute(kan_gemm<2>, cudaFuncAttributeMaxDynamicSharedMemorySize, SMEM_SZ);

    // ---- token mixing ----
    ln_kernel<<<B_ * T_, 256>>>(x, ln1_w, ln1_b, pLn);
    pack_coef<<<(TD_ * KF + 255) / 256, 256>>>(tok_coef, pBh, pBl, TD_);
    pack_w<<<(T_ * TD_ + 255) / 256, 256>>>(tok_lw, pWh, pWl, T_ * TD_);
    feat_kernel<1><<<NTOK / 256, 256>>>(pLn, pFh, pFl);
    // z (M x 256) = F * coef^T + kbias  -> bf16 split
    kan_gemm<0><<<dim3(TD_ / NT, MROWS / MT), 256, SMEM_SZ>>>(
        pFh, pFl, pBh, pBl, tok_kb, nullptr, nullptr, pZh, pZl, KF, TD_);
    // x1 = x + transpose(z * lw^T + lb)
    kan_gemm<1><<<dim3(T_ / NT, MROWS / MT), 256, SMEM_SZ>>>(
        pZh, pZl, pWh, pWl, tok_lb, x, pX1, nullptr, nullptr, TD_, T_);

    // ---- channel mixing ----
    ln_kernel<<<B_ * T_, 256>>>(pX1, ln2_w, ln2_b, pLn);
    pack_coef<<<(1024 * KF + 255) / 256, 256>>>(ch_coef, pBh, pBl, 1024);
    pack_w<<<(C_ * 1024 + 255) / 256, 256>>>(ch_lw, pWh, pWl, C_ * 1024);
    feat_kernel<0><<<NTOK / 256, 256>>>(pLn, pFh, pFl);
    // z2 (M x 1024) = F * coef^T + kbias -> bf16 split
    kan_gemm<0><<<dim3(1024 / NT, MROWS / MT), 256, SMEM_SZ>>>(
        pFh, pFl, pBh, pBl, ch_kb, nullptr, nullptr, pZh, pZl, KF, 1024);
    // out = x1 + (z2 * lw^T + lb)
    kan_gemm<2><<<dim3(C_ / NT, MROWS / MT), 256, SMEM_SZ>>>(
        pZh, pZl, pWh, pWl, ch_lb, pX1, out, nullptr, nullptr, 1024, C_);
}

// round 4
// speedup vs baseline: 3.3505x; 1.1609x over previous
#include <cuda_runtime.h>
#include <cuda_bf16.h>
#include <cuda_fp16.h>
#include <math.h>
#include <stdint.h>

// Problem constants
#define B_  32
#define T_  512
#define C_  512
#define TD_ 256
#define G_  3
#define MROWS (B_ * C_)        // 16384 (== B_*T_)
#define KF  (512 * 6)          // 3072 expanded-feature K
#define KCH 6144               // ch KAN concatenated K' = 2*KF
#define KCL 2048               // ch linear concatenated K' = 2*1024
#define NTOK 8388608           // B*T*C

// GEMM tiling (both kernels): CTA 128x256, BK=64
#define MT 128
#define NT 256
#define BK 64

// bf16x3 kernel smem: per buffer Ah 16K | Al 16K | Bh 32K | Bl 32K = 96K, x2
#define OFF_AL 16384u
#define OFF_BH 32768u
#define OFF_BL 65536u
#define BUF_STRIDE 98304u
#define SMEM3_SZ (2 * 98304)

// std fp16 kernel smem: per buffer A 16K | B 32K = 48K, 4 stages
#define SOFF_B 16384u
#define SBUF 49152u
#define SMEMS_SZ (4 * 49152)

#define STG_S 261              // epilogue stage row stride (floats)

// ----------------------------------------------------------------------------
// Scratch arena (single device global, stage-aliased)
// ----------------------------------------------------------------------------
#define MB (1024ull * 1024ull)
#define OFF_FEAT    0ull              // tok: Fh(96MB)@0, Fl(96MB)@96MB | ch: F16(192MB)@0
#define OFF_TOKFL   (96ull  * MB)
#define OFF_Z       (192ull * MB)     // tok: Zh(8MB)@192, Zl(8MB)@200 | ch: Z216(64MB)@192
#define OFF_TOKZL   (200ull * MB)
#define OFF_TBH     (256ull * MB)     // tok coef hi (1.5MB)
#define OFF_TBL     (258ull * MB)     // tok coef lo
#define OFF_TWH     (260ull * MB)     // tok lw hi (0.25MB)
#define OFF_TWL     (262ull * MB)     // tok lw lo
#define OFF_C16     (264ull * MB)     // ch coef fp16 dup (12MB)
#define OFF_W16     (276ull * MB)     // ch lw fp16 dup (2MB)
#define OFF_LN      (278ull * MB)     // fp32 LN buf (32MB)
#define OFF_X1      (310ull * MB)     // fp32 x1 (32MB)
#define SCRATCH_SZ  (342ull * MB)
__device__ __align__(256) char g_scratch[SCRATCH_SZ];

// ----------------------------------------------------------------------------
// PTX helpers
// ----------------------------------------------------------------------------
__device__ __forceinline__ uint32_t smem_u32(const void* p) {
    uint32_t a;
    asm("{ .reg .u64 t; cvta.to.shared.u64 t, %1; cvt.u32.u64 %0, t; }" : "=r"(a) : "l"(p));
    return a;
}
__device__ __forceinline__ void cpasync16(uint32_t dst, const void* src) {
    asm volatile("cp.async.cg.shared.global [%0], [%1], 16;" :: "r"(dst), "l"(src));
}
__device__ __forceinline__ void cp_commit() {
    asm volatile("cp.async.commit_group;" ::: "memory");
}
__device__ __forceinline__ void cp_wait0() {
    asm volatile("cp.async.wait_group 0;" ::: "memory");
}
__device__ __forceinline__ void cp_wait1() {
    asm volatile("cp.async.wait_group 1;" ::: "memory");
}
__device__ __forceinline__ void cp_wait2() {
    asm volatile("cp.async.wait_group 2;" ::: "memory");
}
__device__ __forceinline__ void ldsm4(uint32_t addr, uint32_t r[4]) {
    asm volatile("ldmatrix.sync.aligned.m8n8.x4.shared.b16 {%0,%1,%2,%3}, [%4];"
                 : "=r"(r[0]), "=r"(r[1]), "=r"(r[2]), "=r"(r[3]) : "r"(addr));
}
__device__ __forceinline__ void mma_bf16(float d[4], const uint32_t a[4], const uint32_t b[2]) {
    asm volatile(
        "mma.sync.aligned.m16n8k16.row.col.f32.bf16.bf16.f32 "
        "{%0,%1,%2,%3}, {%4,%5,%6,%7}, {%8,%9}, {%0,%1,%2,%3};"
        : "+f"(d[0]), "+f"(d[1]), "+f"(d[2]), "+f"(d[3])
        : "r"(a[0]), "r"(a[1]), "r"(a[2]), "r"(a[3]), "r"(b[0]), "r"(b[1]));
}
__device__ __forceinline__ void mma_f16(float d[4], const uint32_t a[4], const uint32_t b[2]) {
    asm volatile(
        "mma.sync.aligned.m16n8k16.row.col.f32.f16.f16.f32 "
        "{%0,%1,%2,%3}, {%4,%5,%6,%7}, {%8,%9}, {%0,%1,%2,%3};"
        : "+f"(d[0]), "+f"(d[1]), "+f"(d[2]), "+f"(d[3])
        : "r"(a[0]), "r"(a[1]), "r"(a[2]), "r"(a[3]), "r"(b[0]), "r"(b[1]));
}
__device__ __forceinline__ void split_bf(float v, __nv_bfloat16& h, __nv_bfloat16& l) {
    h = __float2bfloat16(v);
    l = __float2bfloat16(v - __bfloat162float(h));
}
__device__ __forceinline__ void split_h(float v, __half& h, __half& l) {
    h = __float2half_rn(v);
    l = __float2half_rn(v - __half2float(h));
}

// ----------------------------------------------------------------------------
// LayerNorm (stage 1 only): one block per row of 512, 256 threads
// ----------------------------------------------------------------------------
__global__ void ln_kernel(const float* __restrict__ x,
                          const float* __restrict__ w,
                          const float* __restrict__ b,
                          float* __restrict__ out)
{
    int row = blockIdx.x;
    const float2* xr = (const float2*)(x + (size_t)row * C_);
    float2 v = xr[threadIdx.x];
    float s  = v.x + v.y;
    float sq = v.x * v.x + v.y * v.y;

    __shared__ float ss[8], sqq[8];
    __shared__ float s_mean, s_rstd;
    #pragma unroll
    for (int o = 16; o > 0; o >>= 1) {
        s  += __shfl_down_sync(0xffffffffu, s,  o);
        sq += __shfl_down_sync(0xffffffffu, sq, o);
    }
    int lane = threadIdx.x & 31, wid = threadIdx.x >> 5;
    if (lane == 0) { ss[wid] = s; sqq[wid] = sq; }
    __syncthreads();
    if (wid == 0) {
        float a = (lane < 8) ? ss[lane]  : 0.f;
        float q = (lane < 8) ? sqq[lane] : 0.f;
        #pragma unroll
        for (int o = 4; o > 0; o >>= 1) {
            a += __shfl_down_sync(0xffffffffu, a, o);
            q += __shfl_down_sync(0xffffffffu, q, o);
        }
        if (lane == 0) {
            float m = a * (1.0f / C_);
            float var = q * (1.0f / C_) - m * m;
            s_mean = m;
            s_rstd = rsqrtf(var + 1e-5f);
        }
    }
    __syncthreads();
    float m = s_mean, r = s_rstd;
    float2 wv = ((const float2*)w)[threadIdx.x];
    float2 bv = ((const float2*)b)[threadIdx.x];
    float2 ov;
    ov.x = (v.x - m) * r * wv.x + bv.x;
    ov.y = (v.y - m) * r * wv.y + bv.y;
    ((float2*)(out + (size_t)row * C_))[threadIdx.x] = ov;
}

// ----------------------------------------------------------------------------
// Pack tok coef (2, 256, 512, 3) -> bf16 hi/lo (256 x KF)
// ----------------------------------------------------------------------------
__global__ void pack_coef3(const float* __restrict__ coef,
                           __nv_bfloat16* __restrict__ Bh,
                           __nv_bfloat16* __restrict__ Bl, int O)
{
    int total = O * KF;
    int idx = blockIdx.x * blockDim.x + threadIdx.x;
    if (idx >= total) return;
    int o    = idx / KF;
    int r    = idx % KF;
    int i    = r / 6;
    int rr   = r % 6;
    int g    = rr >> 1;
    int trig = rr & 1;
    float v = coef[(((size_t)trig * O + o) * 512 + i) * G_ + g];
    split_bf(v, Bh[idx], Bl[idx]);
}

// Pack tok lw -> bf16 hi/lo
__global__ void pack_w3(const float* __restrict__ w,
                        __nv_bfloat16* __restrict__ Wh,
                        __nv_bfloat16* __restrict__ Wl, int total)
{
    int idx = blockIdx.x * blockDim.x + threadIdx.x;
    if (idx >= total) return;
    split_bf(w[idx], Wh[idx], Wl[idx]);
}

// Pack ch coef (2, 1024, 512, 3) -> fp16 duplicated (1024 x 6144): [C16|C16]
__global__ void pack_coef16(const float* __restrict__ coef,
                            __half* __restrict__ out, int O)
{
    int total = O * KF;
    int idx = blockIdx.x * blockDim.x + threadIdx.x;
    if (idx >= total) return;
    int o    = idx / KF;
    int r    = idx % KF;
    int i    = r / 6;
    int rr   = r % 6;
    int g    = rr >> 1;
    int trig = rr & 1;
    __half h = __float2half_rn(coef[(((size_t)trig * O + o) * 512 + i) * G_ + g]);
    out[(size_t)o * KCH + r]      = h;
    out[(size_t)o * KCH + KF + r] = h;
}

// Pack ch lw (512 x 1024) -> fp16 duplicated (512 x 2048): [W16|W16]
__global__ void pack_w16(const float* __restrict__ w, __half* __restrict__ out)
{
    int idx = blockIdx.x * blockDim.x + threadIdx.x;   // 512*1024
    if (idx >= 512 * 1024) return;
    int n = idx >> 10, k = idx & 1023;
    __half h = __float2half_rn(w[idx]);
    out[(size_t)n * KCL + k]        = h;
    out[(size_t)n * KCL + 1024 + k] = h;
}

// ----------------------------------------------------------------------------
// Token feature expansion (smem-tiled transpose): bf16 hi/lo
// block = (b, i-tile 256, c-tile 32); grid (16, 2, 32)
// ----------------------------------------------------------------------------
__global__ __launch_bounds__(256)
void feat_tok(const float* __restrict__ ln,
              __nv_bfloat16* __restrict__ Fh,
              __nv_bfloat16* __restrict__ Fl)
{
    __shared__ float s[256 * 33];
    const int t  = threadIdx.x;
    const int c0 = blockIdx.x * 32;
    const int i0 = blockIdx.y * 256;
    const int b  = blockIdx.z;

    #pragma unroll
    for (int it = 0; it < 8; it++) {
        int r  = it * 32 + (t >> 3);
        int cc = (t & 7) * 4;
        float4 v = *(const float4*)(ln + ((size_t)(b * T_ + i0 + r)) * C_ + c0 + cc);
        s[r * 33 + cc]     = v.x;
        s[r * 33 + cc + 1] = v.y;
        s[r * 33 + cc + 2] = v.z;
        s[r * 33 + cc + 3] = v.w;
    }
    __syncthreads();

    const int w = t >> 5, lane = t & 31;
    #pragma unroll
    for (int rep = 0; rep < 4; rep++) {
        const int cl = w * 4 + rep;
        const int n  = b * C_ + c0 + cl;
        #pragma unroll
        for (int it2 = 0; it2 < 8; it2++) {
            int il = it2 * 32 + lane;
            float v = s[il * 33 + cl];
            float s1, c1;
            sincosf(v, &s1, &c1);
            float c2 = 2.f * c1 * c1 - 1.f;
            float s2 = 2.f * s1 * c1;
            float c3 = 2.f * c1 * c2 - c1;
            float s3 = 2.f * c1 * s2 - s1;
            __nv_bfloat16 h[6], l[6];
            split_bf(c1, h[0], l[0]); split_bf(s1, h[1], l[1]);
            split_bf(c2, h[2], l[2]); split_bf(s2, h[3], l[3]);
            split_bf(c3, h[4], l[4]); split_bf(s3, h[5], l[5]);
            size_t base = (size_t)n * KF + (size_t)(i0 + il) * 6;
            __nv_bfloat162* ph = (__nv_bfloat162*)(Fh + base);
            ph[0] = __nv_bfloat162(h[0], h[1]);
            ph[1] = __nv_bfloat162(h[2], h[3]);
            ph[2] = __nv_bfloat162(h[4], h[5]);
            __nv_bfloat162* pl = (__nv_bfloat162*)(Fl + base);
            pl[0] = __nv_bfloat162(l[0], l[1]);
            pl[1] = __nv_bfloat162(l[2], l[3]);
            pl[2] = __nv_bfloat162(l[4], l[5]);
        }
    }
}

// ----------------------------------------------------------------------------
// Channel stage: fused LN2 + feature expansion -> fp16 hi/lo concat layout
// F16 row m (len 6144): [hi(3072) | lo(3072)]. One block per (b,t) row.
// ----------------------------------------------------------------------------
__global__ __launch_bounds__(256)
void feat_ch(const float* __restrict__ x1,
             const float* __restrict__ w,
             const float* __restrict__ b,
             __half* __restrict__ F16)
{
    int row = blockIdx.x;
    const float2* xr = (const float2*)(x1 + (size_t)row * C_);
    float2 v = xr[threadIdx.x];
    float s  = v.x + v.y;
    float sq = v.x * v.x + v.y * v.y;

    __shared__ float ss[8], sqq[8];
    __shared__ float s_mean, s_rstd;
    #pragma unroll
    for (int o = 16; o > 0; o >>= 1) {
        s  += __shfl_down_sync(0xffffffffu, s,  o);
        sq += __shfl_down_sync(0xffffffffu, sq, o);
    }
    int lane = threadIdx.x & 31, wid = threadIdx.x >> 5;
    if (lane == 0) { ss[wid] = s; sqq[wid] = sq; }
    __syncthreads();
    if (wid == 0) {
        float a = (lane < 8) ? ss[lane]  : 0.f;
        float q = (lane < 8) ? sqq[lane] : 0.f;
        #pragma unroll
        for (int o = 4; o > 0; o >>= 1) {
            a += __shfl_down_sync(0xffffffffu, a, o);
            q += __shfl_down_sync(0xffffffffu, q, o);
        }
        if (lane == 0) {
            float m = a * (1.0f / C_);
            float var = q * (1.0f / C_) - m * m;
            s_mean = m;
            s_rstd = rsqrtf(var + 1e-5f);
        }
    }
    __syncthreads();
    float m = s_mean, r = s_rstd;
    float2 wv = ((const float2*)w)[threadIdx.x];
    float2 bv = ((const float2*)b)[threadIdx.x];
    float ln0 = (v.x - m) * r * wv.x + bv.x;
    float ln1 = (v.y - m) * r * wv.y + bv.y;

    #pragma unroll
    for (int q = 0; q < 2; q++) {
        float vv = q ? ln1 : ln0;
        int c = threadIdx.x * 2 + q;
        float s1, c1;
        sincosf(vv, &s1, &c1);
        float c2 = 2.f * c1 * c1 - 1.f;
        float s2 = 2.f * s1 * c1;
        float c3 = 2.f * c1 * c2 - c1;
        float s3 = 2.f * c1 * s2 - s1;
        __half h[6], l[6];
        split_h(c1, h[0], l[0]); split_h(s1, h[1], l[1]);
        split_h(c2, h[2], l[2]); split_h(s2, h[3], l[3]);
        split_h(c3, h[4], l[4]); split_h(s3, h[5], l[5]);
        size_t base = (size_t)row * KCH + (size_t)c * 6;
        __half2* ph = (__half2*)(F16 + base);
        ph[0] = __half2(h[0], h[1]);
        ph[1] = __half2(h[2], h[3]);
        ph[2] = __half2(h[4], h[5]);
        __half2* pl = (__half2*)(F16 + base + KF);
        pl[0] = __half2(l[0], l[1]);
        pl[1] = __half2(l[2], l[3]);
        pl[2] = __half2(l[4], l[5]);
    }
}

// ----------------------------------------------------------------------------
// bf16x3-split TN GEMM (token path): D = Ah*Bh + Ah*Bl + Al*Bh + bias
// MODE 0: write bf16 hi/lo split of D to outH/outL (row stride Ntot)
// MODE 1: token linear: m=(b,c), n=t; outF[(b*T+n)*C+c] = res[..] + D
// ----------------------------------------------------------------------------
template<int MODE>
__global__ __launch_bounds__(256, 1)
void kan_gemm3(const __nv_bfloat16* __restrict__ Ah, const __nv_bfloat16* __restrict__ Al,
               const __nv_bfloat16* __restrict__ Bh, const __nv_bfloat16* __restrict__ Bl,
               const float* __restrict__ bias, const float* __restrict__ res,
               float* __restrict__ outF,
               __nv_bfloat16* __restrict__ outH, __nv_bfloat16* __restrict__ outL,
               int K, int Ntot)
{
    extern __shared__ char smem[];
    const uint32_t sbase = smem_u32(smem);
    const int tid  = threadIdx.x;
    const int wid  = tid >> 5;
    const int lane = tid & 31;
    const int m0 = blockIdx.y * MT;
    const int n0 = blockIdx.x * NT;
    const int wm = wid >> 2;
    const int wn = wid & 3;

    float acc[4][8][4];
    #pragma unroll
    for (int i = 0; i < 4; i++)
        #pragma unroll
        for (int j = 0; j < 8; j++)
            #pragma unroll
            for (int q = 0; q < 4; q++) acc[i][j][q] = 0.f;

    const int NC = K >> 6;

    auto load_chunk = [&](int kc, int buf) {
        const uint32_t sb = sbase + (uint32_t)buf * BUF_STRIDE;
        const size_t kcol = (size_t)kc * BK;
        #pragma unroll
        for (int it = 0; it < 4; it++) {
            int u = tid + it * 256;
            int r = u >> 3, cch = u & 7;
            uint32_t off = r * 128 + ((cch ^ (r & 7)) << 4);
            cpasync16(sb + off, (const char*)(Ah + (size_t)(m0 + r) * K + kcol) + cch * 16);
            cpasync16(sb + OFF_AL + off, (const char*)(Al + (size_t)(m0 + r) * K + kcol) + cch * 16);
        }
        #pragma unroll
        for (int it = 0; it < 8; it++) {
            int u = tid + it * 256;
            int r = u >> 3, cch = u & 7;
            uint32_t off = r * 128 + ((cch ^ (r & 7)) << 4);
            cpasync16(sb + OFF_BH + off, (const char*)(Bh + (size_t)(n0 + r) * K + kcol) + cch * 16);
            cpasync16(sb + OFF_BL + off, (const char*)(Bl + (size_t)(n0 + r) * K + kcol) + cch * 16);
        }
        cp_commit();
    };

    load_chunk(0, 0);

    const int lr = lane & 7;
    const int lq = lane >> 3;

    for (int kc = 0; kc < NC; kc++) {
        if (kc + 1 < NC) { load_chunk(kc + 1, (kc + 1) & 1); cp_wait1(); }
        else             { cp_wait0(); }
        __syncthreads();

        const uint32_t sb = sbase + (uint32_t)(kc & 1) * BUF_STRIDE;
        #pragma unroll
        for (int k16 = 0; k16 < 4; k16++) {
            uint32_t ah[4][4], al[4][4];
            #pragma unroll
            for (int i = 0; i < 4; i++) {
                int row = wm * 64 + i * 16 + lr + (lq & 1) * 8;
                int ch  = (k16 * 2 + (lq >> 1)) ^ (row & 7);
                uint32_t ad = row * 128 + (ch << 4);
                ldsm4(sb + ad, ah[i]);
                ldsm4(sb + OFF_AL + ad, al[i]);
            }
            #pragma unroll
            for (int jp = 0; jp < 4; jp++) {
                int row = wn * 64 + jp * 16 + lr + (lq >> 1) * 8;
                int ch  = (k16 * 2 + (lq & 1)) ^ (row & 7);
                uint32_t ad = row * 128 + (ch << 4);
                uint32_t th[4], tl[4];
                ldsm4(sb + OFF_BH + ad, th);
                ldsm4(sb + OFF_BL + ad, tl);
                #pragma unroll
                for (int i = 0; i < 4; i++) {
                    mma_bf16(acc[i][2*jp],   ah[i], th);
                    mma_bf16(acc[i][2*jp],   ah[i], tl);
                    mma_bf16(acc[i][2*jp],   al[i], th);
                    mma_bf16(acc[i][2*jp+1], ah[i], th + 2);
                    mma_bf16(acc[i][2*jp+1], ah[i], tl + 2);
                    mma_bf16(acc[i][2*jp+1], al[i], th + 2);
                }
            }
        }
        __syncthreads();
    }

    // stage accumulators to smem
    float* stage = (float*)smem;
    {
        const int g = lane >> 2, t2 = (lane & 3) * 2;
        #pragma unroll
        for (int i = 0; i < 4; i++) {
            int row = wm * 64 + i * 16 + g;
            #pragma unroll
            for (int j = 0; j < 8; j++) {
                int col = wn * 64 + j * 8 + t2;
                stage[row * STG_S + col]           = acc[i][j][0];
                stage[row * STG_S + col + 1]       = acc[i][j][1];
                stage[(row + 8) * STG_S + col]     = acc[i][j][2];
                stage[(row + 8) * STG_S + col + 1] = acc[i][j][3];
            }
        }
    }
    __syncthreads();

    if (MODE == 0) {
        for (int u = tid; u < 128 * (NT / 2); u += 256) {
            int r = u >> 7;
            int c = (u & 127) * 2;
            float v0 = stage[r * STG_S + c]     + bias[n0 + c];
            float v1 = stage[r * STG_S + c + 1] + bias[n0 + c + 1];
            __nv_bfloat16 h0, l0, h1, l1;
            split_bf(v0, h0, l0);
            split_bf(v1, h1, l1);
            size_t o = ((size_t)(m0 + r) * Ntot + n0 + c) >> 1;
            ((__nv_bfloat162*)outH)[o] = __nv_bfloat162(h0, h1);
            ((__nv_bfloat162*)outL)[o] = __nv_bfloat162(l0, l1);
        }
    } else {
        const int b  = m0 >> 9;
        const int c0 = m0 & 511;
        for (int nl = wid; nl < NT; nl += 8) {
            int n = n0 + nl;
            float bn = bias[n];
            size_t obase = ((size_t)(b * T_ + n)) * C_ + c0;
            #pragma unroll
            for (int cc = 0; cc < 4; cc++) {
                int c = lane + cc * 32;
                outF[obase + c] = res[obase + c] + stage[c * STG_S + nl] + bn;
            }
        }
    }
}

// ----------------------------------------------------------------------------
// fp16 single-stream TN GEMM (channel path), 4-stage pipeline
// MODE 0: fp16 hi/lo split out: outH[m*Ntot+n] hi, outH[m*Ntot+loOff+n] lo
// MODE 2: outF[m*C_+n0+n] = res[..] + D + bias
// ----------------------------------------------------------------------------
template<int MODE>
__global__ __launch_bounds__(256, 1)
void gemm_std(const __half* __restrict__ A, const __half* __restrict__ Bm,
              const float* __restrict__ bias, const float* __restrict__ res,
              float* __restrict__ outF, __half* __restrict__ outH,
              int K, int Ntot, int loOff)
{
    extern __shared__ char smem[];
    const uint32_t sbase = smem_u32(smem);
    const int tid  = threadIdx.x;
    const int wid  = tid >> 5;
    const int lane = tid & 31;
    const int m0 = blockIdx.y * MT;
    const int n0 = blockIdx.x * NT;
    const int wm = wid >> 2;
    const int wn = wid & 3;

    float acc[4][8][4];
    #pragma unroll
    for (int i = 0; i < 4; i++)
        #pragma unroll
        for (int j = 0; j < 8; j++)
            #pragma unroll
            for (int q = 0; q < 4; q++) acc[i][j][q] = 0.f;

    const int NC = K >> 6;

    auto load_chunk = [&](int kc, int buf) {
        const uint32_t sb = sbase + (uint32_t)buf * SBUF;
        const size_t kcol = (size_t)kc * BK;
        #pragma unroll
        for (int it = 0; it < 4; it++) {
            int u = tid + it * 256;
            int r = u >> 3, cch = u & 7;
            uint32_t off = r * 128 + ((cch ^ (r & 7)) << 4);
            cpasync16(sb + off, (const char*)(A + (size_t)(m0 + r) * K + kcol) + cch * 16);
        }
        #pragma unroll
        for (int it = 0; it < 8; it++) {
            int u = tid + it * 256;
            int r = u >> 3, cch = u & 7;
            uint32_t off = r * 128 + ((cch ^ (r & 7)) << 4);
            cpasync16(sb + SOFF_B + off, (const char*)(Bm + (size_t)(n0 + r) * K + kcol) + cch * 16);
        }
    };

    #pragma unroll
    for (int s = 0; s < 3; s++) {
        if (s < NC) load_chunk(s, s);
        cp_commit();
    }

    const int lr = lane & 7;
    const int lq = lane >> 3;

    for (int kc = 0; kc < NC; kc++) {
        cp_wait2();
        __syncthreads();

        const uint32_t sb = sbase + (uint32_t)(kc & 3) * SBUF;
        #pragma unroll
        for (int k16 = 0; k16 < 4; k16++) {
            uint32_t ah[4][4];
            #pragma unroll
            for (int i = 0; i < 4; i++) {
                int row = wm * 64 + i * 16 + lr + (lq & 1) * 8;
                int ch  = (k16 * 2 + (lq >> 1)) ^ (row & 7);
                ldsm4(sb + row * 128 + (ch << 4), ah[i]);
            }
            #pragma unroll
            for (int jp = 0; jp < 4; jp++) {
                int row = wn * 64 + jp * 16 + lr + (lq >> 1) * 8;
                int ch  = (k16 * 2 + (lq & 1)) ^ (row & 7);
                uint32_t tb[4];
                ldsm4(sb + SOFF_B + row * 128 + (ch << 4), tb);
                #pragma unroll
                for (int i = 0; i < 4; i++) {
                    mma_f16(acc[i][2*jp],   ah[i], tb);
                    mma_f16(acc[i][2*jp+1], ah[i], tb + 2);
                }
            }
        }
        int nk = kc + 3;
        if (nk < NC) load_chunk(nk, nk & 3);
        cp_commit();
    }
    cp_wait0();
    __syncthreads();

    // stage accumulators to smem
    float* stage = (float*)smem;
    {
        const int g = lane >> 2, t2 = (lane & 3) * 2;
        #pragma unroll
        for (int i = 0; i < 4; i++) {
            int row = wm * 64 + i * 16 + g;
            #pragma unroll
            for (int j = 0; j < 8; j++) {
                int col = wn * 64 + j * 8 + t2;
                stage[row * STG_S + col]           = acc[i][j][0];
                stage[row * STG_S + col + 1]       = acc[i][j][1];
                stage[(row + 8) * STG_S + col]     = acc[i][j][2];
                stage[(row + 8) * STG_S + col + 1] = acc[i][j][3];
            }
        }
    }
    __syncthreads();

    if (MODE == 0) {
        for (int u = tid; u < 128 * (NT / 2); u += 256) {
            int r = u >> 7;
            int c = (u & 127) * 2;
            float v0 = stage[r * STG_S + c]     + bias[n0 + c];
            float v1 = stage[r * STG_S + c + 1] + bias[n0 + c + 1];
            __half h0, l0, h1, l1;
            split_h(v0, h0, l0);
            split_h(v1, h1, l1);
            size_t rowb = (size_t)(m0 + r) * Ntot;
            ((__half2*)(outH + rowb + n0 + c))[0]         = __half2(h0, h1);
            ((__half2*)(outH + rowb + loOff + n0 + c))[0] = __half2(l0, l1);
        }
    } else {
        for (int u = tid; u < 128 * (NT / 4); u += 256) {
            int r = u >> 6;
            int c = (u & 63) * 4;
            size_t base = (size_t)(m0 + r) * C_ + n0 + c;
            float4 rv = *(const float4*)(res + base);
            float4 ov;
            ov.x = rv.x + stage[r * STG_S + c]     + bias[n0 + c];
            ov.y = rv.y + stage[r * STG_S + c + 1] + bias[n0 + c + 1];
            ov.z = rv.z + stage[r * STG_S + c + 2] + bias[n0 + c + 2];
            ov.w = rv.w + stage[r * STG_S + c + 3] + bias[n0 + c + 3];
            *(float4*)(outF + base) = ov;
        }
    }
}

// ----------------------------------------------------------------------------
// Launch
// ----------------------------------------------------------------------------
extern "C" void kernel_launch(void* const* d_in, const int* in_sizes, int n_in,
                              void* d_out, int out_size)
{
    const float* x        = (const float*)d_in[0];
    const float* ln1_w    = (const float*)d_in[1];
    const float* ln1_b    = (const float*)d_in[2];
    const float* tok_coef = (const float*)d_in[3];
    const float* tok_kb   = (const float*)d_in[4];
    const float* tok_lw   = (const float*)d_in[5];
    const float* tok_lb   = (const float*)d_in[6];
    const float* ln2_w    = (const float*)d_in[7];
    const float* ln2_b    = (const float*)d_in[8];
    const float* ch_coef  = (const float*)d_in[9];
    const float* ch_kb    = (const float*)d_in[10];
    const float* ch_lw    = (const float*)d_in[11];
    const float* ch_lb    = (const float*)d_in[12];
    float* out = (float*)d_out;

    char* base;
    cudaGetSymbolAddress((void**)&base, g_scratch);
    __nv_bfloat16* pFh  = (__nv_bfloat16*)(base + OFF_FEAT);
    __nv_bfloat16* pFl  = (__nv_bfloat16*)(base + OFF_TOKFL);
    __half*        pF16 = (__half*)       (base + OFF_FEAT);
    __nv_bfloat16* pZh  = (__nv_bfloat16*)(base + OFF_Z);
    __nv_bfloat16* pZl  = (__nv_bfloat16*)(base + OFF_TOKZL);
    __half*        pZ16 = (__half*)       (base + OFF_Z);
    __nv_bfloat16* pTBh = (__nv_bfloat16*)(base + OFF_TBH);
    __nv_bfloat16* pTBl = (__nv_bfloat16*)(base + OFF_TBL);
    __nv_bfloat16* pTWh = (__nv_bfloat16*)(base + OFF_TWH);
    __nv_bfloat16* pTWl = (__nv_bfloat16*)(base + OFF_TWL);
    __half*        pC16 = (__half*)       (base + OFF_C16);
    __half*        pW16 = (__half*)       (base + OFF_W16);
    float*         pLn  = (float*)        (base + OFF_LN);
    float*         pX1  = (float*)        (base + OFF_X1);

    cudaFuncSetAttribute(kan_gemm3<0>, cudaFuncAttributeMaxDynamicSharedMemorySize, SMEM3_SZ);
    cudaFuncSetAttribute(kan_gemm3<1>, cudaFuncAttributeMaxDynamicSharedMemorySize, SMEM3_SZ);
    cudaFuncSetAttribute(gemm_std<0>,  cudaFuncAttributeMaxDynamicSharedMemorySize, SMEMS_SZ);
    cudaFuncSetAttribute(gemm_std<2>,  cudaFuncAttributeMaxDynamicSharedMemorySize, SMEMS_SZ);

    // ---- token mixing (bf16x3, error-critical) ----
    ln_kernel<<<B_ * T_, 256>>>(x, ln1_w, ln1_b, pLn);
    pack_coef3<<<(TD_ * KF + 255) / 256, 256>>>(tok_coef, pTBh, pTBl, TD_);
    pack_w3<<<(T_ * TD_ + 255) / 256, 256>>>(tok_lw, pTWh, pTWl, T_ * TD_);
    feat_tok<<<dim3(C_ / 32, T_ / 256, B_), 256>>>(pLn, pFh, pFl);
    kan_gemm3<0><<<dim3(TD_ / NT, MROWS / MT), 256, SMEM3_SZ>>>(
        pFh, pFl, pTBh, pTBl, tok_kb, nullptr, nullptr, pZh, pZl, KF, TD_);
    kan_gemm3<1><<<dim3(T_ / NT, MROWS / MT), 256, SMEM3_SZ>>>(
        pZh, pZl, pTWh, pTWl, tok_lb, x, pX1, nullptr, nullptr, TD_, T_);

    // ---- channel mixing (fp16 2-term via K-concat) ----
    pack_coef16<<<(1024 * KF + 255) / 256, 256>>>(ch_coef, pC16, 1024);
    pack_w16<<<(512 * 1024 + 255) / 256, 256>>>(ch_lw, pW16);
    feat_ch<<<B_ * T_, 256>>>(pX1, ln2_w, ln2_b, pF16);
    // z2 (M x 1024) = F * coef^T + kbias -> fp16 hi/lo concat (M x 2048)
    gemm_std<0><<<dim3(1024 / NT, MROWS / MT), 256, SMEMS_SZ>>>(
        pF16, pC16, ch_kb, nullptr, nullptr, pZ16, KCH, KCL, 1024);
    // out = x1 + (z2 * lw^T + lb)
    gemm_std<2><<<dim3(C_ / NT, MROWS / MT), 256, SMEMS_SZ>>>(
        pZ16, pW16, ch_lb, pX1, out, nullptr, KCL, 0, 0);
}